// round 1
// baseline (speedup 1.0000x reference)
#include <cuda_runtime.h>
#include <math.h>

static constexpr int T    = 32;
static constexpr int IMGW = 512, IMGH = 512, NIMG = 48;   // 16*3 images of 512x512
static constexpr int TILES = (IMGW / T) * (IMGH / T) * NIMG;  // 12288
static constexpr float FEPS = 1e-8f;

// per-(window,block) partial sums; every slot is written every launch -> deterministic
__device__ double g_partial[3 * TILES];

template <int K>
__global__ __launch_bounds__(256)
void statloss_kernel(const float* __restrict__ pred,
                     const float* __restrict__ target,
                     int winIdx)
{
    constexpr int R  = K / 2;
    constexpr int H  = T + 4 * R;   // x tile extent (halo 2R)
    constexpr int M  = T + 2 * R;   // mean/xc extent (halo R)
    constexpr int XS = H + 1;       // padded strides (bank-conflict relief)
    constexpr int MS = M + 1;

    __shared__ float sX[H * XS];
    __shared__ float sT1[H * MS];
    __shared__ float sT2[H * MS];
    __shared__ float sMEAN[M * MS];
    __shared__ float sC3[M * MS];
    __shared__ float sC4[M * MS];
    __shared__ double sRed[8];

    const int tid = threadIdx.x;
    const int tx  = tid & 31;
    const int ty0 = tid >> 5;       // 0..7 ; each thread owns rows ty0+{0,8,16,24}

    // normalized 1-D gaussian (separable: g2 = outer(g,g), already sum-1)
    float g[K];
    {
        const float sigma = (float)K / 6.0f;
        float s = 0.f;
#pragma unroll
        for (int i = 0; i < K; i++) {
            float c = (float)(i - K / 2);
            g[i] = expf(-c * c / (2.0f * sigma * sigma));
            s += g[i];
        }
#pragma unroll
        for (int i = 0; i < K; i++) g[i] /= s;
    }

    const int gx0 = blockIdx.x * T;
    const int gy0 = blockIdx.y * T;
    const size_t base = (size_t)blockIdx.z * IMGH * IMGW;

    float fmean[2][4], fvar[2][4], fskew[2][4], fkurt[2][4];

    for (int which = 0; which < 2; which++) {
        const float* xin = (which == 0 ? pred : target) + base;

        // ---- load x tile with 2R halo (zero pad outside image) ----
        for (int idx = tid; idx < H * H; idx += 256) {
            int j = idx / H, i = idx - j * H;
            int gy = gy0 - 2 * R + j, gx = gx0 - 2 * R + i;
            float v = 0.f;
            if ((unsigned)gy < (unsigned)IMGH && (unsigned)gx < (unsigned)IMGW)
                v = xin[gy * IMGW + gx];
            sX[j * XS + i] = v;
        }
        __syncthreads();

        // ---- P1: horizontal conv of x and x^2 ----
        for (int idx = tid; idx < H * M; idx += 256) {
            int j = idx / M, i = idx - j * M;
            float a = 0.f, b = 0.f;
#pragma unroll
            for (int d = 0; d < K; d++) {
                float v = sX[j * XS + i + d];
                a += g[d] * v;
                b += g[d] * v * v;
            }
            sT1[j * MS + i] = a;
            sT2[j * MS + i] = b;
        }
        __syncthreads();

        // ---- P2: vertical conv -> MEAN (halo R); s2 only at center pixels ----
        for (int idx = tid; idx < M * M; idx += 256) {
            int m = idx / M, i = idx - m * M;
            float a = 0.f;
#pragma unroll
            for (int d = 0; d < K; d++) a += g[d] * sT1[(m + d) * MS + i];
            sMEAN[m * MS + i] = a;
        }
        float s2q[4];
#pragma unroll
        for (int q = 0; q < 4; q++) {
            int ty = ty0 + 8 * q;
            float b = 0.f;
#pragma unroll
            for (int d = 0; d < K; d++) b += g[d] * sT2[(ty + R + d) * MS + tx + R];
            s2q[q] = b;
        }
        __syncthreads();

        // ---- P3: xc^3, xc^4 on halo-R grid (xc == 0 outside image, matching zero-pad) ----
        for (int idx = tid; idx < M * M; idx += 256) {
            int m = idx / M, i = idx - m * M;
            int gy = gy0 - R + m, gx = gx0 - R + i;
            float c = 0.f;
            if ((unsigned)gy < (unsigned)IMGH && (unsigned)gx < (unsigned)IMGW)
                c = sX[(m + R) * XS + i + R] - sMEAN[m * MS + i];
            float c3 = c * c * c;
            sC3[m * MS + i] = c3;
            sC4[m * MS + i] = c3 * c;
        }
        float meanq[4];
#pragma unroll
        for (int q = 0; q < 4; q++)
            meanq[q] = sMEAN[(ty0 + 8 * q + R) * MS + tx + R];
        __syncthreads();

        // ---- P4: horizontal conv of xc^3 / xc^4 (center cols only) ----
        for (int idx = tid; idx < M * T; idx += 256) {
            int m = idx / T, i = idx - m * T;
            float a = 0.f, b = 0.f;
#pragma unroll
            for (int d = 0; d < K; d++) {
                a += g[d] * sC3[m * MS + i + d];
                b += g[d] * sC4[m * MS + i + d];
            }
            sT1[m * MS + i] = a;
            sT2[m * MS + i] = b;
        }
        __syncthreads();

        // ---- P5: vertical conv -> m3, m4; final features ----
#pragma unroll
        for (int q = 0; q < 4; q++) {
            int ty = ty0 + 8 * q;
            float m3 = 0.f, m4 = 0.f;
#pragma unroll
            for (int d = 0; d < K; d++) {
                m3 += g[d] * sT1[(ty + d) * MS + tx];
                m4 += g[d] * sT2[(ty + d) * MS + tx];
            }
            float mean = meanq[q];
            float var  = fmaxf(s2q[q] - mean * mean, FEPS);
            float sd   = sqrtf(var);
            fmean[which][q] = mean;
            fvar[which][q]  = var;
            fskew[which][q] = m3 / (sd * sd * sd + FEPS);
            fkurt[which][q] = m4 / (var * var + FEPS);
        }
        __syncthreads();   // before smem reuse by next input
    }

    // ---- per-thread loss, block reduce in double ----
    double acc = 0.0;
#pragma unroll
    for (int q = 0; q < 4; q++) {
        acc += 1.0   * (double)fabsf(fmean[0][q] - fmean[1][q]);
        acc += 1.0   * (double)fabsf(fvar[0][q]  - fvar[1][q]);
        acc += 0.5   * (double)fabsf(fskew[0][q] - fskew[1][q]);
        acc += 0.001 * (double)fabsf(fkurt[0][q] - fkurt[1][q]);
    }
#pragma unroll
    for (int o = 16; o > 0; o >>= 1)
        acc += __shfl_down_sync(0xffffffffu, acc, o);
    if ((tid & 31) == 0) sRed[tid >> 5] = acc;
    __syncthreads();
    if (tid < 8) {
        double a = sRed[tid];
#pragma unroll
        for (int o = 4; o > 0; o >>= 1)
            a += __shfl_down_sync(0xffu, a, o);
        if (tid == 0) {
            int blin = (blockIdx.z * gridDim.y + blockIdx.y) * gridDim.x + blockIdx.x;
            g_partial[winIdx * TILES + blin] = a;
        }
    }
}

__global__ void finalize_kernel(float* __restrict__ out)
{
    __shared__ double sRed[256];
    double a = 0.0;
    for (int i = threadIdx.x; i < 3 * TILES; i += 256) a += g_partial[i];
    sRed[threadIdx.x] = a;
    __syncthreads();
    for (int s = 128; s > 0; s >>= 1) {
        if (threadIdx.x < s) sRed[threadIdx.x] += sRed[threadIdx.x + s];
        __syncthreads();
    }
    if (threadIdx.x == 0) {
        const double npix = (double)16 * 3 * 512 * 512;
        out[0] = (float)(sRed[0] / (npix * 12.0));
    }
}

extern "C" void kernel_launch(void* const* d_in, const int* in_sizes, int n_in,
                              void* d_out, int out_size)
{
    const float* pred   = (const float*)d_in[0];
    const float* target = (const float*)d_in[1];

    dim3 grid(IMGW / T, IMGH / T, NIMG);   // 16 x 16 x 48 tiles
    statloss_kernel<3><<<grid, 256>>>(pred, target, 0);
    statloss_kernel<5><<<grid, 256>>>(pred, target, 1);
    statloss_kernel<7><<<grid, 256>>>(pred, target, 2);
    finalize_kernel<<<1, 256>>>((float*)d_out);
}